// round 16
// baseline (speedup 1.0000x reference)
#include <cuda_runtime.h>

#define THREADS 512
#define ITEMS 16
#define TILE (THREADS * ITEMS)   // 8192 elements per half-tile
#define MAX_TILES 65536
#define NW (THREADS / 32)
#define SIDX(i) ((i) + ((i) >> 4))   // smem skew: conflict-free blocked writes

// decoupled-lookback state (per HALF-tile): high 32 = status (0 inv, 1 agg, 2 prefix),
// low 32 = fp32 bits. One 64-bit atomic word => no fence. Atomic publish/poll is
// the fast path on this chip (ld.cg poll +35% slower, padded state +48% slower).
__device__ unsigned long long g_state[MAX_TILES];
__device__ unsigned int g_ticket;

__global__ void rtam_init(int nstate) {
    int i = blockIdx.x * blockDim.x + threadIdx.x;
    if (i < nstate) g_state[i] = 0ULL;
    if (i == 0) g_ticket = 0u;
}

__device__ __forceinline__ unsigned long long pack_sv(unsigned st, float v) {
    return ((unsigned long long)st << 32) | (unsigned long long)__float_as_uint(v);
}
__device__ __forceinline__ float warp_sum(float v) {
    #pragma unroll
    for (int o = 16; o; o >>= 1) v += __shfl_xor_sync(0xFFFFFFFFu, v, o);
    return v;
}
// pure-ALU 5-entry LUT: no smem gather, no bank conflicts
__device__ __forceinline__ float lut5(int c, float t1, float t2, float t3,
                                      float t4, float t5) {
    float a = (c < 2) ? t1 : ((c < 3) ? t2 : t3);
    float b = (c < 5) ? t4 : t5;
    return (c < 4) ? a : b;
}

__global__ void __launch_bounds__(THREADS, 1) rtam_scan(
    const int* __restrict__ ann,
    const float* __restrict__ p_origin,
    const float* __restrict__ p_bd,
    const float* __restrict__ p_d,
    const float* __restrict__ p_s,
    const float* __restrict__ p_inc,
    const float* __restrict__ p_bi,
    float* __restrict__ out,
    int n)
{
    __shared__ float s_out[TILE + TILE / 16];   // half-tile A staging (skewed)
    __shared__ float s_table[8];
    __shared__ float s_warp[NW];
    __shared__ float s_excl;
    __shared__ unsigned s_tk;

    const int tid  = threadIdx.x;
    const int lane = tid & 31;
    const int wid  = tid >> 5;

    if (tid == 0) {
        s_tk = atomicAdd(&g_ticket, 1u);
        const float EPS = 0.05f;
        float bd = *p_bd, d = *p_d, s = *p_s, inc = *p_inc, bi = *p_bi;
        s_table[1] = fminf(bd, fminf(0.f, d)) - EPS;                 // big decrease
        s_table[2] = fminf(fmaxf(d, bd + EPS), -EPS);                // decrease (clip)
        s_table[3] = s;                                              // same
        s_table[4] = fminf(fmaxf(inc, EPS), bi - EPS);               // increase (clip)
        s_table[5] = fmaxf(bi, fmaxf(0.f, inc) + EPS);               // big increase
        s_table[6] = *p_origin;
    }
    __syncthreads();

    const int tA = 2 * (int)s_tk;        // this CTA owns half-tiles tA and tA+1
    const float origin = s_table[6];
    const float t1 = s_table[1], t2 = s_table[2], t3 = s_table[3];
    const float t4 = s_table[4], t5 = s_table[5];

    const long long baseA = (long long)tA * TILE;
    const long long baseB = baseA + TILE;
    const int remA = (n - baseA > (long long)TILE) ? TILE : (int)(n - baseA);
    const long long remB64 = (long long)n - baseB;
    const int remB = (remB64 > (long long)TILE) ? TILE : (int)remB64; // may be <= 0

    float vals[ITEMS];
    float run;

    // ================= half A: load + serial scan =================
    run = 0.f;
    if (remA >= TILE) {
        const int4* in4 = (const int4*)(ann + baseA);
        #pragma unroll
        for (int k = 0; k < ITEMS / 4; k++) {
            int4 c = in4[tid * (ITEMS / 4) + k];
            run += lut5(c.x, t1, t2, t3, t4, t5); vals[4 * k + 0] = run;
            run += lut5(c.y, t1, t2, t3, t4, t5); vals[4 * k + 1] = run;
            run += lut5(c.z, t1, t2, t3, t4, t5); vals[4 * k + 2] = run;
            run += lut5(c.w, t1, t2, t3, t4, t5); vals[4 * k + 3] = run;
        }
    } else {
        #pragma unroll
        for (int j = 0; j < ITEMS; j++) {
            long long idx = baseA + (long long)tid * ITEMS + j;
            if (idx < (long long)n) run += lut5(ann[idx], t1, t2, t3, t4, t5);
            vals[j] = run;
        }
    }

    // block scan #1
    {
        const float tsum = run;
        float x = tsum;
        #pragma unroll
        for (int o = 1; o < 32; o <<= 1) {
            float y = __shfl_up_sync(0xFFFFFFFFu, x, o);
            if (lane >= o) x += y;
        }
        if (lane == 31) s_warp[wid] = x;
        __syncthreads();
        if (wid == 0) {
            float w = (lane < NW) ? s_warp[lane] : 0.f;
            #pragma unroll
            for (int o = 1; o < NW; o <<= 1) {
                float y = __shfl_up_sync(0xFFFFFFFFu, w, o);
                if (lane >= o) w += y;
            }
            if (lane < NW) s_warp[lane] = w;
        }
        __syncthreads();
        run = (wid > 0 ? s_warp[wid - 1] : 0.f) + (x - tsum);   // thread_exclA
    }
    const float aggA = s_warp[NW - 1];
    // publish aggA EARLY so the front keeps advancing at half-tile granularity
    if (tid == 0)
        atomicExch(&g_state[tA], pack_sv(tA == 0 ? 2u : 1u, aggA));

    // stage A (blocked -> skewed smem), freeing vals for half B
    #pragma unroll
    for (int j = 0; j < ITEMS; j++)
        s_out[SIDX(tid * ITEMS + j)] = run + vals[j];

    // ================= half B: load + serial scan =================
    run = 0.f;
    if (remB >= TILE) {
        const int4* in4 = (const int4*)(ann + baseB);
        #pragma unroll
        for (int k = 0; k < ITEMS / 4; k++) {
            int4 c = in4[tid * (ITEMS / 4) + k];
            run += lut5(c.x, t1, t2, t3, t4, t5); vals[4 * k + 0] = run;
            run += lut5(c.y, t1, t2, t3, t4, t5); vals[4 * k + 1] = run;
            run += lut5(c.z, t1, t2, t3, t4, t5); vals[4 * k + 2] = run;
            run += lut5(c.w, t1, t2, t3, t4, t5); vals[4 * k + 3] = run;
        }
    } else {
        #pragma unroll
        for (int j = 0; j < ITEMS; j++) {
            long long idx = baseB + (long long)tid * ITEMS + j;
            if (idx >= 0 && idx < (long long)n)
                run += lut5(ann[idx], t1, t2, t3, t4, t5);
            vals[j] = run;
        }
    }

    __syncthreads();   // s_warp reuse + staging complete

    // block scan #2
    float thread_exclB;
    {
        const float tsum = run;
        float x = tsum;
        #pragma unroll
        for (int o = 1; o < 32; o <<= 1) {
            float y = __shfl_up_sync(0xFFFFFFFFu, x, o);
            if (lane >= o) x += y;
        }
        if (lane == 31) s_warp[wid] = x;
        __syncthreads();
        if (wid == 0) {
            float w = (lane < NW) ? s_warp[lane] : 0.f;
            #pragma unroll
            for (int o = 1; o < NW; o <<= 1) {
                float y = __shfl_up_sync(0xFFFFFFFFu, w, o);
                if (lane >= o) w += y;
            }
            if (lane < NW) s_warp[lane] = w;
        }
        __syncthreads();
        thread_exclB = (wid > 0 ? s_warp[wid - 1] : 0.f) + (x - tsum);
    }
    const float aggB = s_warp[NW - 1];

    // ====== warp 0: publish aggB, ONE lookback, publish both prefixes ======
    if (wid == 0) {
        if (tA == 0) {
            if (lane == 0) {
                atomicExch(&g_state[1], pack_sv(2u, aggA + aggB));
                s_excl = 0.f;
            }
        } else {
            if (lane == 0)
                atomicExch(&g_state[tA + 1], pack_sv(1u, aggB));
            float excl = 0.f;
            int look = tA - 1;
            for (;;) {
                int idx = look - lane;
                unsigned long long v = (idx >= 0) ? atomicAdd(&g_state[idx], 0ULL)
                                                  : pack_sv(2u, 0.f);
                unsigned st = (unsigned)(v >> 32);
                float val = __uint_as_float((unsigned)(v & 0xFFFFFFFFULL));
                unsigned pm = __ballot_sync(0xFFFFFFFFu, st == 2u);
                unsigned am = __ballot_sync(0xFFFFFFFFu, st >= 1u);
                if (pm) {
                    int p = __ffs(pm) - 1;
                    unsigned need = (p == 31) ? 0xFFFFFFFFu : ((1u << (p + 1)) - 1u);
                    if ((am & need) == need) {
                        excl += warp_sum((lane <= p) ? val : 0.f);
                        break;
                    }
                } else if (am == 0xFFFFFFFFu) {
                    excl += warp_sum(val);
                    look -= 32;
                }
            }
            if (lane == 0) {
                atomicExch(&g_state[tA],     pack_sv(2u, excl + aggA));
                atomicExch(&g_state[tA + 1], pack_sv(2u, excl + aggA + aggB));
                s_excl = excl;
            }
        }
    }
    __syncthreads();

    const float ofsA = origin + s_excl;
    const float ofsB = ofsA + aggA;

    // ====== store half A: strided from skewed smem (out[baseA+1 ..]) ======
    if (remA >= TILE) {
        float* op = out + baseA;               // 16B-aligned
        if (tid < 3) op[1 + tid] = ofsA + s_out[SIDX(tid)];   // out[baseA+1..3]
        float4* o4 = (float4*)(op + 4);
        const int NV = (TILE - 4) / 4;         // covers out[baseA+4 .. baseA+8191]
        for (int v = tid; v < NV; v += THREADS) {
            int i = 3 + 4 * v;
            float4 r;
            r.x = ofsA + s_out[SIDX(i + 0)];
            r.y = ofsA + s_out[SIDX(i + 1)];
            r.z = ofsA + s_out[SIDX(i + 2)];
            r.w = ofsA + s_out[SIDX(i + 3)];
            o4[v] = r;
        }
        // out[baseA+TILE] == out[baseB] covered by half B's slot 0
    } else {
        for (int i = tid; i < remA; i += THREADS)
            out[baseA + 1 + i] = ofsA + s_out[SIDX(i)];
    }

    // ====== store half B: aligned direct blocked (j-shift scheme) ======
    // prefB(t) == out[baseB + 16t]; slot j value = prefB + (j ? valsB[j-1] : 0)
    const float prefB = ofsB + thread_exclB;
    if (remB >= TILE) {
        float4* o4 = (float4*)(out + baseB + tid * ITEMS);   // 16B-aligned
        float4 r;
        r.x = prefB;            r.y = prefB + vals[0];
        r.z = prefB + vals[1];  r.w = prefB + vals[2];
        o4[0] = r;
        #pragma unroll
        for (int k = 0; k < 3; k++) {
            r.x = prefB + vals[3 + 4 * k];
            r.y = prefB + vals[4 + 4 * k];
            r.z = prefB + vals[5 + 4 * k];
            r.w = prefB + vals[6 + 4 * k];
            o4[1 + k] = r;
        }
        // TAIL (the R14 bug-fix): out[baseB+TILE] belongs to THIS CTA —
        // the next CTA's coverage starts at its baseA+1. remB >= TILE
        // guarantees baseB + TILE <= n; for the last CTA this is out[n].
        if (tid == THREADS - 1)
            out[baseB + TILE] = prefB + vals[15];
    } else if (remB >= 0) {
        #pragma unroll
        for (int j = 0; j < ITEMS; j++) {
            int i = tid * ITEMS + j;
            if (i <= remB)
                out[baseB + i] = prefB + (j ? vals[j - 1] : 0.f);
        }
    }

    if (tA == 0 && tid == 0) out[0] = origin;
}

extern "C" void kernel_launch(void* const* d_in, const int* in_sizes, int n_in,
                              void* d_out, int out_size) {
    const int*   ann    = (const int*)d_in[0];
    const float* origin = (const float*)d_in[1];
    const float* bd     = (const float*)d_in[2];
    const float* d      = (const float*)d_in[3];
    const float* s      = (const float*)d_in[4];
    const float* inc    = (const float*)d_in[5];
    const float* bi     = (const float*)d_in[6];
    float* out = (float*)d_out;

    int n = in_sizes[0];
    int ntiles = (n + TILE - 1) / TILE;           // half-tiles (4096 for 2^25)
    int nstate = ntiles + 2;
    if (nstate > MAX_TILES) nstate = MAX_TILES;
    int nctas = (ntiles + 1) / 2;                 // 2048 CTAs

    rtam_init<<<(nstate + 255) / 256, 256>>>(nstate);
    rtam_scan<<<nctas, THREADS>>>(ann, origin, bd, d, s, inc, bi, out, n);
}

// round 17
// speedup vs baseline: 1.2642x; 1.2642x over previous
#include <cuda_runtime.h>

#define THREADS 512
#define ITEMS 16
#define TILE (THREADS * ITEMS)   // 8192 elements per half-tile
#define MAX_TILES 65536
#define NW (THREADS / 32)
#define SIDX(i) ((i) + ((i) >> 4))   // smem skew: conflict-free blocked writes

// decoupled-lookback state (per HALF-tile): high 32 = status (0 inv, 1 agg, 2 prefix),
// low 32 = fp32 bits. One 64-bit atomic word => no fence. Atomic publish/poll is
// the fast path on this chip (ld.cg poll +35% slower, padded state +48% slower).
__device__ unsigned long long g_state[MAX_TILES];
__device__ unsigned int g_ticket;

__global__ void rtam_init(int nstate) {
    int i = blockIdx.x * blockDim.x + threadIdx.x;
    if (i < nstate) g_state[i] = 0ULL;
    if (i == 0) g_ticket = 0u;
}

__device__ __forceinline__ unsigned long long pack_sv(unsigned st, float v) {
    return ((unsigned long long)st << 32) | (unsigned long long)__float_as_uint(v);
}
__device__ __forceinline__ float warp_sum(float v) {
    #pragma unroll
    for (int o = 16; o; o >>= 1) v += __shfl_xor_sync(0xFFFFFFFFu, v, o);
    return v;
}
// pure-ALU 5-entry LUT: no smem gather, no bank conflicts
__device__ __forceinline__ float lut5(int c, float t1, float t2, float t3,
                                      float t4, float t5) {
    float a = (c < 2) ? t1 : ((c < 3) ? t2 : t3);
    float b = (c < 5) ? t4 : t5;
    return (c < 4) ? a : b;
}
// 0 -> 0.0 variant (padding codes in partial tiles)
__device__ __forceinline__ float lut0(int c, float t1, float t2, float t3,
                                      float t4, float t5) {
    return c ? lut5(c, t1, t2, t3, t4, t5) : 0.f;
}

__global__ void __launch_bounds__(THREADS, 2) rtam_scan(
    const int* __restrict__ ann,
    const float* __restrict__ p_origin,
    const float* __restrict__ p_bd,
    const float* __restrict__ p_d,
    const float* __restrict__ p_s,
    const float* __restrict__ p_inc,
    const float* __restrict__ p_bi,
    float* __restrict__ out,
    int n)
{
    __shared__ float s_out[TILE + TILE / 16];   // half-tile A staging (skewed)
    __shared__ float s_table[8];
    __shared__ float s_warp[NW];
    __shared__ float s_excl;
    __shared__ unsigned s_tk;

    const int tid  = threadIdx.x;
    const int lane = tid & 31;
    const int wid  = tid >> 5;

    if (tid == 0) {
        s_tk = atomicAdd(&g_ticket, 1u);
        const float EPS = 0.05f;
        float bd = *p_bd, d = *p_d, s = *p_s, inc = *p_inc, bi = *p_bi;
        s_table[1] = fminf(bd, fminf(0.f, d)) - EPS;                 // big decrease
        s_table[2] = fminf(fmaxf(d, bd + EPS), -EPS);                // decrease (clip)
        s_table[3] = s;                                              // same
        s_table[4] = fminf(fmaxf(inc, EPS), bi - EPS);               // increase (clip)
        s_table[5] = fmaxf(bi, fmaxf(0.f, inc) + EPS);               // big increase
        s_table[6] = *p_origin;
    }
    __syncthreads();

    const int tA = 2 * (int)s_tk;        // this CTA owns half-tiles tA and tA+1
    const float origin = s_table[6];
    const float t1 = s_table[1], t2 = s_table[2], t3 = s_table[3];
    const float t4 = s_table[4], t5 = s_table[5];

    const long long baseA = (long long)tA * TILE;
    const long long baseB = baseA + TILE;
    const int remA = (n - baseA > (long long)TILE) ? TILE : (int)(n - baseA);
    const long long remB64 = (long long)n - baseB;
    const int remB = (remB64 > (long long)TILE) ? TILE : (int)remB64; // may be <= 0

    // ================= half A: load + serial scan (vals in regs) =================
    {
        float vals[ITEMS];
        float run = 0.f;
        if (remA >= TILE) {
            const int4* in4 = (const int4*)(ann + baseA);
            #pragma unroll
            for (int k = 0; k < ITEMS / 4; k++) {
                int4 c = in4[tid * (ITEMS / 4) + k];
                run += lut5(c.x, t1, t2, t3, t4, t5); vals[4 * k + 0] = run;
                run += lut5(c.y, t1, t2, t3, t4, t5); vals[4 * k + 1] = run;
                run += lut5(c.z, t1, t2, t3, t4, t5); vals[4 * k + 2] = run;
                run += lut5(c.w, t1, t2, t3, t4, t5); vals[4 * k + 3] = run;
            }
        } else {
            #pragma unroll
            for (int j = 0; j < ITEMS; j++) {
                long long idx = baseA + (long long)tid * ITEMS + j;
                if (idx < (long long)n) run += lut5(ann[idx], t1, t2, t3, t4, t5);
                vals[j] = run;
            }
        }

        // block scan #1
        const float tsum = run;
        float x = tsum;
        #pragma unroll
        for (int o = 1; o < 32; o <<= 1) {
            float y = __shfl_up_sync(0xFFFFFFFFu, x, o);
            if (lane >= o) x += y;
        }
        if (lane == 31) s_warp[wid] = x;
        __syncthreads();
        if (wid == 0) {
            float w = (lane < NW) ? s_warp[lane] : 0.f;
            #pragma unroll
            for (int o = 1; o < NW; o <<= 1) {
                float y = __shfl_up_sync(0xFFFFFFFFu, w, o);
                if (lane >= o) w += y;
            }
            if (lane < NW) s_warp[lane] = w;
        }
        __syncthreads();
        const float thread_exclA = (wid > 0 ? s_warp[wid - 1] : 0.f) + (x - tsum);
        const float aggA = s_warp[NW - 1];
        // publish aggA EARLY: front advances at half-tile granularity
        if (tid == 0)
            atomicExch(&g_state[tA], pack_sv(tA == 0 ? 2u : 1u, aggA));

        // stage A (blocked -> skewed smem); vals die here
        #pragma unroll
        for (int j = 0; j < ITEMS; j++)
            s_out[SIDX(tid * ITEMS + j)] = thread_exclA + vals[j];
    }
    const float aggA = s_warp[NW - 1];   // still valid (no writes since scan #1)

    // ================= half B: load, byte-pack codes (4 regs), sum ===============
    unsigned pk[ITEMS / 4];
    float runB = 0.f;
    if (remB >= TILE) {
        const int4* in4 = (const int4*)(ann + baseB);
        #pragma unroll
        for (int k = 0; k < ITEMS / 4; k++) {
            int4 c = in4[tid * (ITEMS / 4) + k];
            pk[k] = (unsigned)c.x | ((unsigned)c.y << 8) |
                    ((unsigned)c.z << 16) | ((unsigned)c.w << 24);
            runB += lut5(c.x, t1, t2, t3, t4, t5);
            runB += lut5(c.y, t1, t2, t3, t4, t5);
            runB += lut5(c.z, t1, t2, t3, t4, t5);
            runB += lut5(c.w, t1, t2, t3, t4, t5);
        }
    } else {
        #pragma unroll
        for (int k = 0; k < ITEMS / 4; k++) {
            unsigned p = 0;
            #pragma unroll
            for (int b = 0; b < 4; b++) {
                long long idx = baseB + (long long)tid * ITEMS + k * 4 + b;
                int c = (idx >= 0 && idx < (long long)n) ? ann[idx] : 0;
                p |= (unsigned)c << (8 * b);
                runB += lut0(c, t1, t2, t3, t4, t5);
            }
            pk[k] = p;
        }
    }

    __syncthreads();   // A staging complete; s_warp free for scan #2

    // block scan #2
    float thread_exclB;
    {
        const float tsum = runB;
        float x = tsum;
        #pragma unroll
        for (int o = 1; o < 32; o <<= 1) {
            float y = __shfl_up_sync(0xFFFFFFFFu, x, o);
            if (lane >= o) x += y;
        }
        if (lane == 31) s_warp[wid] = x;
        __syncthreads();
        if (wid == 0) {
            float w = (lane < NW) ? s_warp[lane] : 0.f;
            #pragma unroll
            for (int o = 1; o < NW; o <<= 1) {
                float y = __shfl_up_sync(0xFFFFFFFFu, w, o);
                if (lane >= o) w += y;
            }
            if (lane < NW) s_warp[lane] = w;
        }
        __syncthreads();
        thread_exclB = (wid > 0 ? s_warp[wid - 1] : 0.f) + (x - tsum);
    }
    const float aggB = s_warp[NW - 1];

    // ====== warp 0: publish aggB, ONE lookback, publish both prefixes ======
    if (wid == 0) {
        if (tA == 0) {
            if (lane == 0) {
                atomicExch(&g_state[1], pack_sv(2u, aggA + aggB));
                s_excl = 0.f;
            }
        } else {
            if (lane == 0)
                atomicExch(&g_state[tA + 1], pack_sv(1u, aggB));
            float excl = 0.f;
            int look = tA - 1;
            for (;;) {
                int idx = look - lane;
                unsigned long long v = (idx >= 0) ? atomicAdd(&g_state[idx], 0ULL)
                                                  : pack_sv(2u, 0.f);
                unsigned st = (unsigned)(v >> 32);
                float val = __uint_as_float((unsigned)(v & 0xFFFFFFFFULL));
                unsigned pm = __ballot_sync(0xFFFFFFFFu, st == 2u);
                unsigned am = __ballot_sync(0xFFFFFFFFu, st >= 1u);
                if (pm) {
                    int p = __ffs(pm) - 1;
                    unsigned need = (p == 31) ? 0xFFFFFFFFu : ((1u << (p + 1)) - 1u);
                    if ((am & need) == need) {
                        excl += warp_sum((lane <= p) ? val : 0.f);
                        break;
                    }
                } else if (am == 0xFFFFFFFFu) {
                    excl += warp_sum(val);
                    look -= 32;
                }
            }
            if (lane == 0) {
                atomicExch(&g_state[tA],     pack_sv(2u, excl + aggA));
                atomicExch(&g_state[tA + 1], pack_sv(2u, excl + aggA + aggB));
                s_excl = excl;
            }
        }
    }
    __syncthreads();

    const float ofsA = origin + s_excl;

    // ====== store half A: strided from skewed smem, out[baseA+1 .. baseA+8191] ======
    if (remA >= TILE) {
        float* op = out + baseA;               // 16B-aligned
        if (tid < 3) op[1 + tid] = ofsA + s_out[SIDX(tid)];   // out[baseA+1..3]
        float4* o4 = (float4*)(op + 4);
        const int NV = (TILE - 4) / 4;         // covers out[baseA+4 .. baseA+8191]
        for (int v = tid; v < NV; v += THREADS) {
            int i = 3 + 4 * v;
            float4 r;
            r.x = ofsA + s_out[SIDX(i + 0)];
            r.y = ofsA + s_out[SIDX(i + 1)];
            r.z = ofsA + s_out[SIDX(i + 2)];
            r.w = ofsA + s_out[SIDX(i + 3)];
            o4[v] = r;
        }
        // out[baseB] covered by half B's slot 0
    } else {
        for (int i = tid; i < remA; i += THREADS)
            out[baseA + 1 + i] = ofsA + s_out[SIDX(i)];
    }

    // ====== store half B: direct blocked j-shift, recomputed from pk ======
    // prefB(t) == out[baseB + 16t]; slot j value = prefB + (prefix through j-1)
    const float prefB = ofsA + aggA + thread_exclB;
    if (remB >= TILE) {
        float4* o4 = (float4*)(out + baseB + tid * ITEMS);   // 16B-aligned
        float acc = 0.f;
        #pragma unroll
        for (int k = 0; k < ITEMS / 4; k++) {
            unsigned p = pk[k];
            float4 r;
            r.x = prefB + acc; acc += lut5((int)(p       & 0xFF), t1, t2, t3, t4, t5);
            r.y = prefB + acc; acc += lut5((int)((p>> 8) & 0xFF), t1, t2, t3, t4, t5);
            r.z = prefB + acc; acc += lut5((int)((p>>16) & 0xFF), t1, t2, t3, t4, t5);
            r.w = prefB + acc; acc += lut5((int)((p>>24) & 0xFF), t1, t2, t3, t4, t5);
            o4[k] = r;
        }
        // tail: out[baseB+TILE] belongs to THIS CTA (next CTA starts at +1);
        // remB >= TILE guarantees baseB + TILE <= n. Last CTA: this is out[n].
        if (tid == THREADS - 1)
            out[baseB + TILE] = prefB + acc;
    } else if (remB >= 0) {
        float acc = 0.f;
        #pragma unroll
        for (int j = 0; j < ITEMS; j++) {
            int i = tid * ITEMS + j;
            if (i <= remB) out[baseB + i] = prefB + acc;
            int c = (int)((pk[j >> 2] >> (8 * (j & 3))) & 0xFF);
            acc += lut0(c, t1, t2, t3, t4, t5);
        }
    }

    if (tA == 0 && tid == 0) out[0] = origin;
}

extern "C" void kernel_launch(void* const* d_in, const int* in_sizes, int n_in,
                              void* d_out, int out_size) {
    const int*   ann    = (const int*)d_in[0];
    const float* origin = (const float*)d_in[1];
    const float* bd     = (const float*)d_in[2];
    const float* d      = (const float*)d_in[3];
    const float* s      = (const float*)d_in[4];
    const float* inc    = (const float*)d_in[5];
    const float* bi     = (const float*)d_in[6];
    float* out = (float*)d_out;

    int n = in_sizes[0];
    int ntiles = (n + TILE - 1) / TILE;           // half-tiles (4096 for 2^25)
    int nstate = ntiles + 2;
    if (nstate > MAX_TILES) nstate = MAX_TILES;
    int nctas = (ntiles + 1) / 2;                 // 2048 CTAs

    rtam_init<<<(nstate + 255) / 256, 256>>>(nstate);
    rtam_scan<<<nctas, THREADS>>>(ann, origin, bd, d, s, inc, bi, out, n);
}